// round 1
// baseline (speedup 1.0000x reference)
#include <cuda_runtime.h>

#define THREADS 256
#define TB      64
#define IN_DIM  65
#define H1      128
#define H2      64
#define OUT_DIM 256

// shared-memory layout (float offsets)
#define OFF_W1T 0
#define OFF_W2T (OFF_W1T + IN_DIM*H1)     // 8320
#define OFF_W3T (OFF_W2T + H1*H2)         // +8192
#define OFF_B1  (OFF_W3T + H2*OUT_DIM)    // +16384
#define OFF_B2  (OFF_B1 + H1)
#define OFF_B3  (OFF_B2 + H2)
#define OFF_IN  (OFF_B3 + OUT_DIM)        // 65*64
#define OFF_X1  (OFF_IN + IN_DIM*TB)      // 128*64
#define OFF_X2  (OFF_X1 + H1*TB)          // 64*64
#define OFF_SC  (OFF_X2 + H2*TB)          // 64 ints
#define SMEM_FLOATS (OFF_SC + TB)
#define SMEM_BYTES  (SMEM_FLOATS * 4)

__global__ void __launch_bounds__(THREADS, 1)
policy_kernel(const float* __restrict__ gIn, const int* __restrict__ gScaleTab,
              const float* __restrict__ gW1, const float* __restrict__ gB1,
              const float* __restrict__ gW2, const float* __restrict__ gB2,
              const float* __restrict__ gW3, const float* __restrict__ gB3,
              float* __restrict__ gProbs, float* __restrict__ gMask,
              int Bsz, int numTiles)
{
    extern __shared__ float sm[];
    float* sW1t = sm + OFF_W1T;   // [k=65][c=128]
    float* sW2t = sm + OFF_W2T;   // [k=128][c=64]
    float* sW3t = sm + OFF_W3T;   // [k=64][c=256]
    float* sB1  = sm + OFF_B1;
    float* sB2  = sm + OFF_B2;
    float* sB3  = sm + OFF_B3;
    float* sIn  = sm + OFF_IN;    // [k=65][r=64]   (transposed)
    float* sX1  = sm + OFF_X1;    // [c=128][r=64]  (transposed)
    float* sX2  = sm + OFF_X2;    // [c=64][r=64]   (transposed)
    int*   sSc  = (int*)(sm + OFF_SC);

    const int tid  = threadIdx.x;
    const int lane = tid & 31;
    const int warp = tid >> 5;
    const int rg   = tid & 15;   // row group (4 rows each)
    const int cg   = tid >> 4;   // col group

    // ---- one-time: stage all weights transposed into smem ----
    for (int idx = tid; idx < IN_DIM*H1; idx += THREADS) {
        int c = idx / IN_DIM, k = idx - c*IN_DIM;
        sW1t[k*H1 + c] = gW1[idx];
    }
    for (int idx = tid; idx < H1*H2; idx += THREADS) {
        int c = idx >> 7, k = idx & 127;
        sW2t[k*H2 + c] = gW2[idx];
    }
    for (int idx = tid; idx < H2*OUT_DIM; idx += THREADS) {
        int c = idx >> 6, k = idx & 63;
        sW3t[k*OUT_DIM + c] = gW3[idx];
    }
    for (int i = tid; i < H1; i += THREADS)      sB1[i] = gB1[i];
    for (int i = tid; i < H2; i += THREADS)      sB2[i] = gB2[i];
    for (int i = tid; i < OUT_DIM; i += THREADS) sB3[i] = gB3[i];

    for (int tile = blockIdx.x; tile < numTiles; tile += gridDim.x) {
        const int rowBase = tile * TB;
        __syncthreads();   // previous tile's smem consumers done (also covers weight staging)

        // ---- load input tile, transposed ----
        for (int idx = tid; idx < TB*IN_DIM; idx += THREADS) {
            int r = idx / IN_DIM, k = idx - r*IN_DIM;
            int row = rowBase + r;
            float v = 0.f;
            if (row < Bsz) v = gIn[(size_t)rowBase*IN_DIM + idx];
            sIn[k*TB + r] = v;
            if (k == IN_DIM-1) {
                int di = (int)v;
                if (di < 0) di = 0;
                if (di > 15) di = 15;
                sSc[r] = (row < Bsz) ? gScaleTab[di] : OUT_DIM;
            }
        }
        __syncthreads();

        // ---- layer 1: x1 = relu(in @ W1^T + b1), 4 rows x 8 cols / thread ----
        {
            float acc[4][8];
            #pragma unroll
            for (int i = 0; i < 4; ++i)
                #pragma unroll
                for (int j = 0; j < 8; ++j) acc[i][j] = 0.f;

            #pragma unroll 5
            for (int k = 0; k < IN_DIM; ++k) {
                float4 a  = *(const float4*)(sIn  + k*TB + rg*4);
                float4 w0 = *(const float4*)(sW1t + k*H1 + cg*8);
                float4 w1 = *(const float4*)(sW1t + k*H1 + cg*8 + 4);
                float av[4] = {a.x, a.y, a.z, a.w};
                float wv[8] = {w0.x, w0.y, w0.z, w0.w, w1.x, w1.y, w1.z, w1.w};
                #pragma unroll
                for (int i = 0; i < 4; ++i)
                    #pragma unroll
                    for (int j = 0; j < 8; ++j)
                        acc[i][j] = fmaf(av[i], wv[j], acc[i][j]);
            }
            #pragma unroll
            for (int j = 0; j < 8; ++j) {
                int c = cg*8 + j;
                float b = sB1[c];
                float4 v;
                v.x = fmaxf(acc[0][j] + b, 0.f);
                v.y = fmaxf(acc[1][j] + b, 0.f);
                v.z = fmaxf(acc[2][j] + b, 0.f);
                v.w = fmaxf(acc[3][j] + b, 0.f);
                *(float4*)(sX1 + c*TB + rg*4) = v;
            }
        }
        __syncthreads();

        // ---- layer 2: x2 = relu(x1 @ W2^T + b2), 4 rows x 4 cols / thread ----
        {
            float acc[4][4];
            #pragma unroll
            for (int i = 0; i < 4; ++i)
                #pragma unroll
                for (int j = 0; j < 4; ++j) acc[i][j] = 0.f;

            #pragma unroll 8
            for (int k = 0; k < H1; ++k) {
                float4 a = *(const float4*)(sX1  + k*TB + rg*4);
                float4 w = *(const float4*)(sW2t + k*H2 + cg*4);
                float av[4] = {a.x, a.y, a.z, a.w};
                float wv[4] = {w.x, w.y, w.z, w.w};
                #pragma unroll
                for (int i = 0; i < 4; ++i)
                    #pragma unroll
                    for (int j = 0; j < 4; ++j)
                        acc[i][j] = fmaf(av[i], wv[j], acc[i][j]);
            }
            #pragma unroll
            for (int j = 0; j < 4; ++j) {
                int c = cg*4 + j;
                float b = sB2[c];
                float4 v;
                v.x = fmaxf(acc[0][j] + b, 0.f);
                v.y = fmaxf(acc[1][j] + b, 0.f);
                v.z = fmaxf(acc[2][j] + b, 0.f);
                v.w = fmaxf(acc[3][j] + b, 0.f);
                *(float4*)(sX2 + c*TB + rg*4) = v;
            }
        }
        __syncthreads();

        // ---- layer 3 + masked softmax: warp owns 8 rows, cols = lane + 32*i ----
        {
            float acc[8][8];
            #pragma unroll
            for (int i = 0; i < 8; ++i)
                #pragma unroll
                for (int j = 0; j < 8; ++j) acc[i][j] = 0.f;

            #pragma unroll 4
            for (int k = 0; k < H2; ++k) {
                float4 a0 = *(const float4*)(sX2 + k*TB + warp*8);
                float4 a1 = *(const float4*)(sX2 + k*TB + warp*8 + 4);
                float av[8] = {a0.x, a0.y, a0.z, a0.w, a1.x, a1.y, a1.z, a1.w};
                float wv[8];
                #pragma unroll
                for (int i = 0; i < 8; ++i) wv[i] = sW3t[k*OUT_DIM + lane + 32*i];
                #pragma unroll
                for (int r = 0; r < 8; ++r)
                    #pragma unroll
                    for (int i = 0; i < 8; ++i)
                        acc[r][i] = fmaf(av[r], wv[i], acc[r][i]);
            }

            #pragma unroll
            for (int rr = 0; rr < 8; ++rr) {
                int r   = warp*8 + rr;
                int row = rowBase + r;
                int scale = sSc[r];
                float v[8];
                float m = -3.0e38f;
                #pragma unroll
                for (int i = 0; i < 8; ++i) {
                    int col = lane + 32*i;
                    v[i] = acc[rr][i] + sB3[col];
                    if (col < scale) m = fmaxf(m, v[i]);
                }
                #pragma unroll
                for (int off = 16; off > 0; off >>= 1)
                    m = fmaxf(m, __shfl_xor_sync(0xffffffffu, m, off));
                float ssum = 0.f;
                #pragma unroll
                for (int i = 0; i < 8; ++i) {
                    int col = lane + 32*i;
                    float e = (col < scale) ? __expf(v[i] - m) : 0.f;
                    v[i] = e;
                    ssum += e;
                }
                #pragma unroll
                for (int off = 16; off > 0; off >>= 1)
                    ssum += __shfl_xor_sync(0xffffffffu, ssum, off);
                float inv = 1.f / ssum;

                if (row < Bsz) {
                    float* po = gProbs + (size_t)row * OUT_DIM;
                    #pragma unroll
                    for (int i = 0; i < 8; ++i)
                        po[lane + 32*i] = v[i] * inv;
                    if (gMask) {
                        float* mo = gMask + (size_t)row * OUT_DIM;
                        #pragma unroll
                        for (int i = 0; i < 8; ++i)
                            mo[lane + 32*i] = ((lane + 32*i) < scale) ? 1.f : 0.f;
                    }
                }
            }
        }
    }
}

extern "C" void kernel_launch(void* const* d_in, const int* in_sizes, int n_in,
                              void* d_out, int out_size)
{
    const float* gIn    = (const float*)d_in[0];
    const int*   gScale = (const int*)  d_in[1];
    const float* gW1    = (const float*)d_in[2];
    const float* gB1    = (const float*)d_in[3];
    const float* gW2    = (const float*)d_in[4];
    const float* gB2    = (const float*)d_in[5];
    const float* gW3    = (const float*)d_in[6];
    const float* gB3    = (const float*)d_in[7];

    int Bsz = in_sizes[0] / IN_DIM;
    int numTiles = (Bsz + TB - 1) / TB;

    float* gProbs = (float*)d_out;
    float* gMask  = nullptr;
    long long need2 = 2LL * Bsz * OUT_DIM;
    if ((long long)out_size >= need2)
        gMask = gProbs + (size_t)Bsz * OUT_DIM;

    cudaFuncSetAttribute(policy_kernel,
                         cudaFuncAttributeMaxDynamicSharedMemorySize, SMEM_BYTES);

    int smCount = 148;
    cudaDeviceGetAttribute(&smCount, cudaDevAttrMultiProcessorCount, 0);
    int grid = numTiles < smCount ? numTiles : smCount;

    policy_kernel<<<grid, THREADS, SMEM_BYTES>>>(
        gIn, gScale, gW1, gB1, gW2, gB2, gW3, gB3,
        gProbs, gMask, Bsz, numTiles);
}

// round 9
// speedup vs baseline: 2.2523x; 2.2523x over previous
#include <cuda_runtime.h>
#include <cuda_bf16.h>
#include <cstdint>

#define THREADS 256
#define TBR     64
#define IN_DIM  65
#define H1      128
#define H2      64
#define OUTD    256

// ---------------- smem byte offsets ----------------
#define OFF_W1H  0        // [128][64] bf16 swz, 16384
#define OFF_W1L  16384
#define OFF_W2H  32768    // [64][128] bf16 swz, 16384
#define OFF_W2L  49152
#define OFF_W3H  65536    // [256][64] bf16 swz, 32768
#define OFF_W3L  98304
#define OFF_AH   131072   // [64][64]  bf16 swz, 8192
#define OFF_AL   139264
#define OFF_X1H  147456   // [64][128] bf16 swz, 16384
#define OFF_X1L  163840
#define OFF_X2H  180224   // [64][64]  bf16 swz, 8192
#define OFF_X2L  188416
#define OFF_B1   196608   // 512
#define OFF_B2   197120   // 256
#define OFF_B3   197376   // 1024
#define OFF_C64  198400   // 512 (W1 column 64, fp32)
#define OFF_DIM  198912   // 256
#define OFF_SC   199168   // 256 (int)
#define OFF_PMAX 199424   // 4*64*4 = 1024
#define OFF_PSUM 200448   // 1024
#define SMEM_BYTES 201472

__device__ __forceinline__ uint32_t smem_u32(const void* p) {
    uint32_t a;
    asm("{ .reg .u64 t; cvta.to.shared.u64 t, %1; cvt.u32.u64 %0, t; }" : "=r"(a) : "l"(p));
    return a;
}
// swizzled byte offset of bf16 element (r,k), row stride sB bytes (sB>=128, pow2)
__device__ __forceinline__ uint32_t swoff(int r, int k, int sB) {
    return (uint32_t)(r * sB) + (uint32_t)((((k >> 3) ^ (r & 7)) << 4) + ((k & 7) << 1));
}
__device__ __forceinline__ float bf16rt(float x) {
    return __bfloat162float(__float2bfloat16_rn(x));
}
__device__ __forceinline__ uint32_t pack2(float a, float b) {
    uint32_t lo = (uint32_t)__bfloat16_as_ushort(__float2bfloat16_rn(a));
    uint32_t hi = (uint32_t)__bfloat16_as_ushort(__float2bfloat16_rn(b));
    return lo | (hi << 16);
}
__device__ __forceinline__ void ldsm4(uint32_t (&a)[4], uint32_t addr) {
    asm volatile("ldmatrix.sync.aligned.m8n8.x4.shared.b16 {%0,%1,%2,%3}, [%4];"
        : "=r"(a[0]), "=r"(a[1]), "=r"(a[2]), "=r"(a[3]) : "r"(addr));
}
__device__ __forceinline__ void mmabf(float (&d)[4], const uint32_t (&a)[4],
                                      uint32_t b0, uint32_t b1) {
    asm volatile("mma.sync.aligned.m16n8k16.row.col.f32.bf16.bf16.f32 "
        "{%0,%1,%2,%3},{%4,%5,%6,%7},{%8,%9},{%0,%1,%2,%3};"
        : "+f"(d[0]), "+f"(d[1]), "+f"(d[2]), "+f"(d[3])
        : "r"(a[0]), "r"(a[1]), "r"(a[2]), "r"(a[3]), "r"(b0), "r"(b1));
}

__global__ void __launch_bounds__(THREADS, 1)
policy_mma_kernel(const float* __restrict__ gIn, const int* __restrict__ gScaleTab,
                  const float* __restrict__ gW1, const float* __restrict__ gB1,
                  const float* __restrict__ gW2, const float* __restrict__ gB2,
                  const float* __restrict__ gW3, const float* __restrict__ gB3,
                  float* __restrict__ gProbs, float* __restrict__ gMask,
                  int Bsz, int numTiles)
{
    extern __shared__ char smc[];
    const int tid  = threadIdx.x;
    const int lane = tid & 31;
    const int wid  = tid >> 5;
    const int wM   = wid >> 2;     // 0..1  (32 rows each)
    const int wN   = wid & 3;      // 0..3
    const uint32_t sb = smem_u32(smc);

    float* sB1  = (float*)(smc + OFF_B1);
    float* sB2  = (float*)(smc + OFF_B2);
    float* sB3  = (float*)(smc + OFF_B3);
    float* sC64 = (float*)(smc + OFF_C64);
    float* sDim = (float*)(smc + OFF_DIM);
    int*   sSc  = (int*)  (smc + OFF_SC);
    float* sPMax = (float*)(smc + OFF_PMAX);
    float* sPSum = (float*)(smc + OFF_PSUM);

    // ---- one-time: stage weights as bf16 hi/lo into swizzled layouts ----
    for (int idx = tid; idx < H1 * 64; idx += THREADS) {          // W1[:, 0:64]
        int n = idx >> 6, k = idx & 63;
        float x = gW1[n * IN_DIM + k];
        float h = bf16rt(x);
        uint32_t o = swoff(n, k, 128);
        *(__nv_bfloat16*)(smc + OFF_W1H + o) = __float2bfloat16_rn(h);
        *(__nv_bfloat16*)(smc + OFF_W1L + o) = __float2bfloat16_rn(x - h);
    }
    for (int n = tid; n < H1; n += THREADS) sC64[n] = gW1[n * IN_DIM + 64];
    for (int idx = tid; idx < H2 * H1; idx += THREADS) {          // W2 [64][128]
        int n = idx >> 7, k = idx & 127;
        float x = gW2[idx];
        float h = bf16rt(x);
        uint32_t o = swoff(n, k, 256);
        *(__nv_bfloat16*)(smc + OFF_W2H + o) = __float2bfloat16_rn(h);
        *(__nv_bfloat16*)(smc + OFF_W2L + o) = __float2bfloat16_rn(x - h);
    }
    for (int idx = tid; idx < OUTD * H2; idx += THREADS) {        // W3 [256][64]
        int n = idx >> 6, k = idx & 63;
        float x = gW3[idx];
        float h = bf16rt(x);
        uint32_t o = swoff(n, k, 128);
        *(__nv_bfloat16*)(smc + OFF_W3H + o) = __float2bfloat16_rn(h);
        *(__nv_bfloat16*)(smc + OFF_W3L + o) = __float2bfloat16_rn(x - h);
    }
    for (int i = tid; i < H1; i += THREADS)   sB1[i] = gB1[i];
    for (int i = tid; i < H2; i += THREADS)   sB2[i] = gB2[i];
    for (int i = tid; i < OUTD; i += THREADS) sB3[i] = gB3[i];
    __syncthreads();

    for (int tile = blockIdx.x; tile < numTiles; tile += gridDim.x) {

        // ---------- phase 0: load input tile (cols 0..63 -> A hi/lo) ----------
        {
            int row = tid >> 2, q = tid & 3;
            long long grow = (long long)tile * TBR + row;
            if (grow < (long long)Bsz) {
                const float* ip = gIn + (size_t)grow * IN_DIM;
                #pragma unroll
                for (int j = 0; j < 8; ++j) {
                    float a = ip[q * 16 + 2 * j], b = ip[q * 16 + 2 * j + 1];
                    float ah = bf16rt(a), bh = bf16rt(b);
                    uint32_t o = swoff(row, q * 16 + 2 * j, 128);
                    *(uint32_t*)(smc + OFF_AH + o) = pack2(ah, bh);
                    *(uint32_t*)(smc + OFF_AL + o) = pack2(a - ah, b - bh);
                }
                if (q == 0) {
                    float dv = ip[64];
                    sDim[row] = dv;
                    int di = (int)dv; di = di < 0 ? 0 : (di > 15 ? 15 : di);
                    sSc[row] = gScaleTab[di];
                }
            } else {
                #pragma unroll
                for (int j = 0; j < 8; ++j) {
                    uint32_t o = swoff(row, q * 16 + 2 * j, 128);
                    *(uint32_t*)(smc + OFF_AH + o) = 0;
                    *(uint32_t*)(smc + OFF_AL + o) = 0;
                }
                if (q == 0) { sDim[row] = 0.f; sSc[row] = OUTD; }
            }
        }
        __syncthreads();

        // ---------- GEMM1: [64x128] = A[64x64] @ W1^T, 3-pass split ----------
        float acc1[2][4][4];
        #pragma unroll
        for (int mi = 0; mi < 2; ++mi)
            #pragma unroll
            for (int ni = 0; ni < 4; ++ni)
                #pragma unroll
                for (int d = 0; d < 4; ++d) acc1[mi][ni][d] = 0.f;
        #pragma unroll
        for (int ks = 0; ks < 4; ++ks) {
            uint32_t Ah[2][4], Al[2][4], Bh[2][4], Bl[2][4];
            #pragma unroll
            for (int mi = 0; mi < 2; ++mi) {
                int r = wM * 32 + mi * 16 + (lane & 15);
                uint32_t kch = (uint32_t)(ks * 2 + (lane >> 4));
                uint32_t o = (uint32_t)(r * 128) + ((kch ^ (uint32_t)(r & 7)) << 4);
                ldsm4(Ah[mi], sb + OFF_AH + o);
                ldsm4(Al[mi], sb + OFF_AL + o);
            }
            #pragma unroll
            for (int np = 0; np < 2; ++np) {
                int n = wN * 32 + np * 16 + ((lane >> 4) << 3) + (lane & 7);
                uint32_t kch = (uint32_t)(ks * 2 + ((lane >> 3) & 1));
                uint32_t o = (uint32_t)(n * 128) + ((kch ^ (uint32_t)(n & 7)) << 4);
                ldsm4(Bh[np], sb + OFF_W1H + o);
                ldsm4(Bl[np], sb + OFF_W1L + o);
            }
            #pragma unroll
            for (int mi = 0; mi < 2; ++mi)
                #pragma unroll
                for (int np = 0; np < 2; ++np)
                    #pragma unroll
                    for (int h = 0; h < 2; ++h) {
                        int ni = np * 2 + h;
                        mmabf(acc1[mi][ni], Ah[mi], Bh[np][h*2], Bh[np][h*2+1]);
                        mmabf(acc1[mi][ni], Ah[mi], Bl[np][h*2], Bl[np][h*2+1]);
                        mmabf(acc1[mi][ni], Al[mi], Bh[np][h*2], Bh[np][h*2+1]);
                    }
        }
        // epilogue 1: bias + exact dim-column correction + relu -> X1 hi/lo
        #pragma unroll
        for (int mi = 0; mi < 2; ++mi) {
            int r0 = wM * 32 + mi * 16 + (lane >> 2), r1 = r0 + 8;
            float d0 = sDim[r0], d1 = sDim[r1];
            #pragma unroll
            for (int ni = 0; ni < 4; ++ni) {
                int c0 = wN * 32 + ni * 8 + ((lane & 3) << 1);
                float bb0 = sB1[c0], bb1 = sB1[c0+1];
                float w0 = sC64[c0], w1 = sC64[c0+1];
                float v00 = fmaxf(acc1[mi][ni][0] + bb0 + d0 * w0, 0.f);
                float v01 = fmaxf(acc1[mi][ni][1] + bb1 + d0 * w1, 0.f);
                float v10 = fmaxf(acc1[mi][ni][2] + bb0 + d1 * w0, 0.f);
                float v11 = fmaxf(acc1[mi][ni][3] + bb1 + d1 * w1, 0.f);
                float h00 = bf16rt(v00), h01 = bf16rt(v01);
                float h10 = bf16rt(v10), h11 = bf16rt(v11);
                uint32_t o0 = swoff(r0, c0, 256), o1 = swoff(r1, c0, 256);
                *(uint32_t*)(smc + OFF_X1H + o0) = pack2(h00, h01);
                *(uint32_t*)(smc + OFF_X1L + o0) = pack2(v00 - h00, v01 - h01);
                *(uint32_t*)(smc + OFF_X1H + o1) = pack2(h10, h11);
                *(uint32_t*)(smc + OFF_X1L + o1) = pack2(v10 - h10, v11 - h11);
            }
        }
        __syncthreads();

        // ---------- GEMM2: [64x64] = X1[64x128] @ W2^T ----------
        float acc2[2][2][4];
        #pragma unroll
        for (int mi = 0; mi < 2; ++mi)
            #pragma unroll
            for (int ni = 0; ni < 2; ++ni)
                #pragma unroll
                for (int d = 0; d < 4; ++d) acc2[mi][ni][d] = 0.f;
        #pragma unroll
        for (int ks = 0; ks < 8; ++ks) {
            uint32_t Ah[2][4], Al[2][4], Bh[4], Bl[4];
            #pragma unroll
            for (int mi = 0; mi < 2; ++mi) {
                int r = wM * 32 + mi * 16 + (lane & 15);
                uint32_t kch = (uint32_t)(ks * 2 + (lane >> 4));
                uint32_t o = (uint32_t)(r * 256) + ((kch ^ (uint32_t)(r & 7)) << 4);
                ldsm4(Ah[mi], sb + OFF_X1H + o);
                ldsm4(Al[mi], sb + OFF_X1L + o);
            }
            {
                int n = wN * 16 + ((lane >> 4) << 3) + (lane & 7);
                uint32_t kch = (uint32_t)(ks * 2 + ((lane >> 3) & 1));
                uint32_t o = (uint32_t)(n * 256) + ((kch ^ (uint32_t)(n & 7)) << 4);
                ldsm4(Bh, sb + OFF_W2H + o);
                ldsm4(Bl, sb + OFF_W2L + o);
            }
            #pragma unroll
            for (int mi = 0; mi < 2; ++mi)
                #pragma unroll
                for (int h = 0; h < 2; ++h) {
                    mmabf(acc2[mi][h], Ah[mi], Bh[h*2], Bh[h*2+1]);
                    mmabf(acc2[mi][h], Ah[mi], Bl[h*2], Bl[h*2+1]);
                    mmabf(acc2[mi][h], Al[mi], Bh[h*2], Bh[h*2+1]);
                }
        }
        // epilogue 2 -> X2 hi/lo
        #pragma unroll
        for (int mi = 0; mi < 2; ++mi) {
            int r0 = wM * 32 + mi * 16 + (lane >> 2), r1 = r0 + 8;
            #pragma unroll
            for (int ni = 0; ni < 2; ++ni) {
                int c0 = wN * 16 + ni * 8 + ((lane & 3) << 1);
                float bb0 = sB2[c0], bb1 = sB2[c0+1];
                float v00 = fmaxf(acc2[mi][ni][0] + bb0, 0.f);
                float v01 = fmaxf(acc2[mi][ni][1] + bb1, 0.f);
                float v10 = fmaxf(acc2[mi][ni][2] + bb0, 0.f);
                float v11 = fmaxf(acc2[mi][ni][3] + bb1, 0.f);
                float h00 = bf16rt(v00), h01 = bf16rt(v01);
                float h10 = bf16rt(v10), h11 = bf16rt(v11);
                uint32_t o0 = swoff(r0, c0, 128), o1 = swoff(r1, c0, 128);
                *(uint32_t*)(smc + OFF_X2H + o0) = pack2(h00, h01);
                *(uint32_t*)(smc + OFF_X2L + o0) = pack2(v00 - h00, v01 - h01);
                *(uint32_t*)(smc + OFF_X2H + o1) = pack2(h10, h11);
                *(uint32_t*)(smc + OFF_X2L + o1) = pack2(v10 - h10, v11 - h11);
            }
        }
        __syncthreads();

        // ---------- GEMM3: [64x256] = X2[64x64] @ W3^T ----------
        float acc3[2][8][4];
        #pragma unroll
        for (int mi = 0; mi < 2; ++mi)
            #pragma unroll
            for (int ni = 0; ni < 8; ++ni)
                #pragma unroll
                for (int d = 0; d < 4; ++d) acc3[mi][ni][d] = 0.f;
        #pragma unroll
        for (int ks = 0; ks < 4; ++ks) {
            uint32_t Ah[2][4], Al[2][4];
            #pragma unroll
            for (int mi = 0; mi < 2; ++mi) {
                int r = wM * 32 + mi * 16 + (lane & 15);
                uint32_t kch = (uint32_t)(ks * 2 + (lane >> 4));
                uint32_t o = (uint32_t)(r * 128) + ((kch ^ (uint32_t)(r & 7)) << 4);
                ldsm4(Ah[mi], sb + OFF_X2H + o);
                ldsm4(Al[mi], sb + OFF_X2L + o);
            }
            #pragma unroll
            for (int np = 0; np < 4; ++np) {
                uint32_t Bh[4], Bl[4];
                int n = wN * 64 + np * 16 + ((lane >> 4) << 3) + (lane & 7);
                uint32_t kch = (uint32_t)(ks * 2 + ((lane >> 3) & 1));
                uint32_t o = (uint32_t)(n * 128) + ((kch ^ (uint32_t)(n & 7)) << 4);
                ldsm4(Bh, sb + OFF_W3H + o);
                ldsm4(Bl, sb + OFF_W3L + o);
                #pragma unroll
                for (int mi = 0; mi < 2; ++mi)
                    #pragma unroll
                    for (int h = 0; h < 2; ++h) {
                        int ni = np * 2 + h;
                        mmabf(acc3[mi][ni], Ah[mi], Bh[h*2], Bh[h*2+1]);
                        mmabf(acc3[mi][ni], Ah[mi], Bl[h*2], Bl[h*2+1]);
                        mmabf(acc3[mi][ni], Al[mi], Bh[h*2], Bh[h*2+1]);
                    }
            }
        }

        // ---------- epilogue 3: bias + masked softmax + stores ----------
        {
            // bias add + per-(warp-row) masked max
            #pragma unroll
            for (int mi = 0; mi < 2; ++mi)
                #pragma unroll
                for (int h = 0; h < 2; ++h) {
                    int r = wM * 32 + mi * 16 + (lane >> 2) + h * 8;
                    int scale = sSc[r];
                    float m = -3.4e38f;
                    #pragma unroll
                    for (int ni = 0; ni < 8; ++ni) {
                        int c0 = wN * 64 + ni * 8 + ((lane & 3) << 1);
                        float v0 = acc3[mi][ni][h*2]   + sB3[c0];
                        float v1 = acc3[mi][ni][h*2+1] + sB3[c0+1];
                        acc3[mi][ni][h*2]   = v0;
                        acc3[mi][ni][h*2+1] = v1;
                        if (c0     < scale) m = fmaxf(m, v0);
                        if (c0 + 1 < scale) m = fmaxf(m, v1);
                    }
                    m = fmaxf(m, __shfl_xor_sync(0xffffffffu, m, 1));
                    m = fmaxf(m, __shfl_xor_sync(0xffffffffu, m, 2));
                    if ((lane & 3) == 0) sPMax[wN * 64 + r] = m;
                }
            __syncthreads();
            #pragma unroll
            for (int mi = 0; mi < 2; ++mi)
                #pragma unroll
                for (int h = 0; h < 2; ++h) {
                    int r = wM * 32 + mi * 16 + (lane >> 2) + h * 8;
                    int scale = sSc[r];
                    float gm = fmaxf(fmaxf(sPMax[r], sPMax[64 + r]),
                                     fmaxf(sPMax[128 + r], sPMax[192 + r]));
                    float s = 0.f;
                    #pragma unroll
                    for (int ni = 0; ni < 8; ++ni) {
                        int c0 = wN * 64 + ni * 8 + ((lane & 3) << 1);
                        float e0 = (c0     < scale) ? __expf(acc3[mi][ni][h*2]   - gm) : 0.f;
                        float e1 = (c0 + 1 < scale) ? __expf(acc3[mi][ni][h*2+1] - gm) : 0.f;
                        acc3[mi][ni][h*2]   = e0;
                        acc3[mi][ni][h*2+1] = e1;
                        s += e0 + e1;
                    }
                    s += __shfl_xor_sync(0xffffffffu, s, 1);
                    s += __shfl_xor_sync(0xffffffffu, s, 2);
                    if ((lane & 3) == 0) sPSum[wN * 64 + r] = s;
                }
            __syncthreads();
            long long rowG0 = (long long)tile * TBR;
            #pragma unroll
            for (int mi = 0; mi < 2; ++mi)
                #pragma unroll
                for (int h = 0; h < 2; ++h) {
                    int r = wM * 32 + mi * 16 + (lane >> 2) + h * 8;
                    long long grow = rowG0 + r;
                    float inv = 1.f / (sPSum[r] + sPSum[64 + r] +
                                       sPSum[128 + r] + sPSum[192 + r]);
                    if (grow < (long long)Bsz) {
                        float* po = gProbs + (size_t)grow * OUTD;
                        #pragma unroll
                        for (int ni = 0; ni < 8; ++ni) {
                            int c0 = wN * 64 + ni * 8 + ((lane & 3) << 1);
                            float2 t;
                            t.x = acc3[mi][ni][h*2]   * inv;
                            t.y = acc3[mi][ni][h*2+1] * inv;
                            *(float2*)(po + c0) = t;
                        }
                    }
                }
            // mask output (coalesced)
            if (gMask) {
                #pragma unroll
                for (int i = 0; i < 16; ++i) {
                    int g = tid + 256 * i;
                    int row = g >> 6, c4 = g & 63;
                    long long grow = rowG0 + row;
                    if (grow < (long long)Bsz) {
                        int sc = sSc[row];
                        int c0 = c4 * 4;
                        float4 t;
                        t.x = (c0     < sc) ? 1.f : 0.f;
                        t.y = (c0 + 1 < sc) ? 1.f : 0.f;
                        t.z = (c0 + 2 < sc) ? 1.f : 0.f;
                        t.w = (c0 + 3 < sc) ? 1.f : 0.f;
                        *(float4*)(gMask + (size_t)grow * OUTD + c0) = t;
                    }
                }
            }
        }
        __syncthreads();   // protect sSc/sDim/A/X buffers before next tile
    }
}

extern "C" void kernel_launch(void* const* d_in, const int* in_sizes, int n_in,
                              void* d_out, int out_size)
{
    const float* gIn    = (const float*)d_in[0];
    const int*   gScale = (const int*)  d_in[1];
    const float* gW1    = (const float*)d_in[2];
    const float* gB1    = (const float*)d_in[3];
    const float* gW2    = (const float*)d_in[4];
    const float* gB2    = (const float*)d_in[5];
    const float* gW3    = (const float*)d_in[6];
    const float* gB3    = (const float*)d_in[7];

    int Bsz = in_sizes[0] / IN_DIM;
    int numTiles = (Bsz + TBR - 1) / TBR;

    float* gProbs = (float*)d_out;
    float* gMask  = nullptr;
    long long need2 = 2LL * Bsz * OUTD;
    if ((long long)out_size >= need2)
        gMask = gProbs + (size_t)Bsz * OUTD;

    cudaFuncSetAttribute(policy_mma_kernel,
                         cudaFuncAttributeMaxDynamicSharedMemorySize, SMEM_BYTES);

    int smCount = 148;
    cudaDeviceGetAttribute(&smCount, cudaDevAttrMultiProcessorCount, 0);
    int grid = numTiles < smCount ? numTiles : smCount;

    policy_mma_kernel<<<grid, THREADS, SMEM_BYTES>>>(
        gIn, gScale, gW1, gB1, gW2, gB2, gW3, gB3,
        gProbs, gMask, Bsz, numTiles);
}